// round 17
// baseline (speedup 1.0000x reference)
#include <cuda_runtime.h>
#include <math.h>

#define BATCH   1024
#define SEQ     200
#define HID     128
#define VOCAB   100000
#define PAD_ID      99998
#define INTEREST_ID 99999
#define NTHR    256

__device__ __forceinline__ float fast_tanh(float x) {
    float y;
    asm("tanh.approx.f32 %0, %1;" : "=f"(y) : "f"(x));
    return y;
}

__device__ __forceinline__ void prefetch_l2(const void* p) {
    asm volatile("prefetch.global.L2 [%0];" :: "l"(p));
}

// ---------------------------------------------------------------------------
// Fused: scores -> masked softmax (max-free) -> scatter-add.
// One CTA per batch row, occ 7 (148*7=1036 >= 1024 -> single wave).
// Unroll x3 + L2 prefetch 6 j-steps ahead (turns cold DRAM LDGs into L2 hits).
// ---------------------------------------------------------------------------
__global__ __launch_bounds__(NTHR, 7) void score_scatter_kernel(
    const float* __restrict__ hs,   // (B, S, H) fp32
    const int*   __restrict__ ids,  // (B, S) int32
    const float* __restrict__ w,    // (H,)
    const float* __restrict__ bp,   // (1,)
    float* __restrict__ out)        // (B, VOCAB) fp32, already zeroed
{
    const int b    = blockIdx.x;
    const int tid  = threadIdx.x;
    const int lane = tid & 31;
    const int warp = tid >> 5;

    __shared__ float s_scores[SEQ];
    __shared__ float red[8];

    // lane l owns H-elements [4l, 4l+4)
    const float4* hb  = reinterpret_cast<const float4*>(hs + (size_t)b * SEQ * HID);
    const float4  key = hb[lane];                               // hidden[b,0,:]
    const float4  wp  = reinterpret_cast<const float4*>(w)[lane];
    const float   bias = bp[0];

    // warm L2 for the first two iterations' rows (j = 0..5)
    if ((lane & 7) == 0) {
        #pragma unroll
        for (int j = 0; j < 6; ++j)
            prefetch_l2((const char*)(hb + (warp + 8 * j) * (HID / 4)) + (lane >> 3) * 128);
    }

    // 25 s-rows per warp: 8 triples (MLP=3) + 1 tail
    #pragma unroll 1
    for (int jo = 0; jo < 24; jo += 3) {
        // prefetch rows 6 j-steps ahead (one prefetch per 128B line)
        if ((lane & 7) == 0) {
            #pragma unroll
            for (int u = 0; u < 3; ++u) {
                const int sp = warp + 8 * (jo + 6 + u);
                if (sp < SEQ)
                    prefetch_l2((const char*)(hb + sp * (HID / 4)) + (lane >> 3) * 128);
            }
        }

        float4 hv[3];
        #pragma unroll
        for (int u = 0; u < 3; ++u)
            hv[u] = hb[(warp + 8 * (jo + u)) * (HID / 4) + lane];

        float p[3];
        #pragma unroll
        for (int u = 0; u < 3; ++u) {
            p[u] = fast_tanh(hv[u].x + key.x) * wp.x
                 + fast_tanh(hv[u].y + key.y) * wp.y
                 + fast_tanh(hv[u].z + key.z) * wp.z
                 + fast_tanh(hv[u].w + key.w) * wp.w;
        }
        #pragma unroll
        for (int o = 16; o; o >>= 1) {
            #pragma unroll
            for (int u = 0; u < 3; ++u)
                p[u] += __shfl_xor_sync(0xffffffffu, p[u], o);
        }
        if (lane == 0) {
            #pragma unroll
            for (int u = 0; u < 3; ++u)
                s_scores[warp + 8 * (jo + u)] = p[u] + bias;
        }
    }
    {   // tail: j = 24 (rows 192..199; prefetched in the jo=18 iteration)
        const int s = warp + 8 * 24;
        float4 hv = hb[s * (HID / 4) + lane];
        float p = fast_tanh(hv.x + key.x) * wp.x
                + fast_tanh(hv.y + key.y) * wp.y
                + fast_tanh(hv.z + key.z) * wp.z
                + fast_tanh(hv.w + key.w) * wp.w;
        #pragma unroll
        for (int o = 16; o; o >>= 1) p += __shfl_xor_sync(0xffffffffu, p, o);
        if (lane == 0) s_scores[s] = p + bias;
    }
    __syncthreads();

    // ---- max-free masked softmax (|score| <= ~9, exp never overflows) ----
    int   my_id = 0;
    float e     = 0.f;
    if (tid < SEQ) {
        my_id = ids[(size_t)b * SEQ + tid];
        const bool valid = (my_id != PAD_ID) && (my_id != INTEREST_ID);
        e = valid ? __expf(s_scores[tid]) : 0.f;
    }

    // single block-reduce: sum of e
    float ssum = e;
    #pragma unroll
    for (int o = 16; o; o >>= 1) ssum += __shfl_xor_sync(0xffffffffu, ssum, o);
    if (lane == 0) red[warp] = ssum;
    __syncthreads();
    if (warp == 0) {
        float tt = red[lane & 7];
        #pragma unroll
        for (int o = 4; o; o >>= 1) tt += __shfl_xor_sync(0xffffffffu, tt, o);
        if (lane == 0) red[0] = tt;
    }
    __syncthreads();
    const float inv_sum = 1.0f / red[0];

    // scatter into this block's private (pre-zeroed) row
    if (e != 0.f) {
        atomicAdd(out + (size_t)b * VOCAB + my_id, e * inv_sum);
    }
}

extern "C" void kernel_launch(void* const* d_in, const int* in_sizes, int n_in,
                              void* d_out, int out_size) {
    const float* hs  = (const float*)d_in[0];
    const int*   ids = (const int*)d_in[1];
    const float* w   = (const float*)d_in[2];
    const float* bp  = (const float*)d_in[3];
    float*       out = (float*)d_out;

    // Driver-tuned zero-fill of the 410 MB output (graph memset node, ~6.8 TB/s).
    cudaMemsetAsync(out, 0, (size_t)out_size * sizeof(float));

    // Reads + fused scatter; ordered after the memset by stream order.
    score_scatter_kernel<<<BATCH, NTHR>>>(hs, ids, w, bp, out);
}